// round 4
// baseline (speedup 1.0000x reference)
#include <cuda_runtime.h>
#include <cuda_bf16.h>
#include <cstdint>

// ============================================================
// LoRALinear on base sm_103 (no 'a' features available!):
//   out = (x @ signs^T) * scale + 2 * ((x@A^T) @ B^T)
// Path: Ampere-style mma.sync m16n8k16 bf16 (HMMA), split x = hi + lo
// for fp32-grade accuracy, LoRA folded into the K dimension.
// ============================================================

#define DINLINE __device__ __forceinline__

// ---------------- scratch (device globals; no allocations allowed) ----------
__device__ __nv_bfloat16 g_signs_bf[4096u * 4096u];   // 32 MB
__device__ float        g_t[8192 * 16];               // t = x @ A^T
__device__ __nv_bfloat16 g_tA[8192 * 64];             // [t_hi | t_lo | t_hi | 0] per row
__device__ __nv_bfloat16 g_tB[4096 * 64];             // [B'hi | B'hi | B'lo | 0], B' = 2*B/scale

// ---------------- PTX helpers (all legal on base sm_103) ----------------
DINLINE uint32_t smem_u32(const void* p) {
    uint32_t a;
    asm("{ .reg .u64 t; cvta.to.shared.u64 t, %1; cvt.u32.u64 %0, t; }"
        : "=r"(a) : "l"(p));
    return a;
}

DINLINE void cpa16(uint32_t s, const void* g) {
    asm volatile("cp.async.cg.shared.global [%0], [%1], 16;" :: "r"(s), "l"(g));
}
#define CP_COMMIT()  asm volatile("cp.async.commit_group;" ::: "memory")
#define CP_WAIT(n)   asm volatile("cp.async.wait_group %0;" :: "n"(n) : "memory")

#define LDSM4(r0, r1, r2, r3, addr)                                        \
    asm volatile("ldmatrix.sync.aligned.m8n8.x4.shared.b16 {%0,%1,%2,%3}, [%4];" \
                 : "=r"(r0), "=r"(r1), "=r"(r2), "=r"(r3) : "r"(addr))

#define MMA16816(d, a, b)                                                  \
    asm volatile("mma.sync.aligned.m16n8k16.row.col.f32.bf16.bf16.f32 "    \
                 "{%0,%1,%2,%3}, {%4,%5,%6,%7}, {%8,%9}, {%0,%1,%2,%3};"   \
                 : "+f"((d)[0]), "+f"((d)[1]), "+f"((d)[2]), "+f"((d)[3])  \
                 : "r"((a)[0]), "r"((a)[1]), "r"((a)[2]), "r"((a)[3]),     \
                   "r"((b)[0]), "r"((b)[1]))

DINLINE float2 lds64(uint32_t addr) {
    float2 v;
    asm volatile("ld.shared.v2.f32 {%0,%1}, [%2];" : "=f"(v.x), "=f"(v.y) : "r"(addr));
    return v;
}

// split a pair of f32 into hi-bf16x2 and lo-bf16x2 (lo = residual)
DINLINE void split2(float2 v, uint32_t& hi, uint32_t& lo) {
    __nv_bfloat162 h = __floats2bfloat162_rn(v.x, v.y);   // .x low half
    hi = *reinterpret_cast<uint32_t*>(&h);
    float rx = v.x - __bfloat162float(h.x);
    float ry = v.y - __bfloat162float(h.y);
    __nv_bfloat162 l2 = __floats2bfloat162_rn(rx, ry);
    lo = *reinterpret_cast<uint32_t*>(&l2);
}

// ---------------- kernel 1: signs f32 -> bf16 (exact for +-1) ----------------
__global__ __launch_bounds__(256) void convert_signs_kernel(const float* __restrict__ s) {
    size_t base = ((size_t)blockIdx.x * 256 + threadIdx.x) * 8;
    float4 a = *(const float4*)(s + base);
    float4 b = *(const float4*)(s + base + 4);
    __nv_bfloat162 p0 = __floats2bfloat162_rn(a.x, a.y);
    __nv_bfloat162 p1 = __floats2bfloat162_rn(a.z, a.w);
    __nv_bfloat162 p2 = __floats2bfloat162_rn(b.x, b.y);
    __nv_bfloat162 p3 = __floats2bfloat162_rn(b.z, b.w);
    uint4 o;
    o.x = *(uint32_t*)&p0; o.y = *(uint32_t*)&p1;
    o.z = *(uint32_t*)&p2; o.w = *(uint32_t*)&p3;
    *(uint4*)(g_signs_bf + base) = o;
}

// ---------------- kernel 2: t[8192,16] = x @ lora_A^T (fp32) ----------------
__global__ __launch_bounds__(256) void lora_t_kernel(const float* __restrict__ x,
                                                     const float* __restrict__ A) {
    __shared__ float4 As4[16 * 128];  // 16 ranks x 512-float K chunk
    __shared__ float ts[64 * 16];
    int tid = threadIdx.x, w = tid >> 5, lane = tid & 31;

    #pragma unroll
    for (int j = 0; j < 4; j++) ts[tid * 4 + j] = 0.f;

    for (int kc = 0; kc < 4096; kc += 512) {
        __syncthreads();
        #pragma unroll
        for (int i = 0; i < 8; i++) {
            int idx = tid + 256 * i;
            int r = idx >> 7, q = idx & 127;
            As4[idx] = *(const float4*)(A + (size_t)r * 4096 + kc + q * 4);
        }
        __syncthreads();
        for (int rr = 0; rr < 8; rr++) {
            int row = blockIdx.x * 64 + w * 8 + rr;
            const float4* xr = (const float4*)(x + (size_t)row * 4096 + kc);
            float acc[16];
            #pragma unroll
            for (int r = 0; r < 16; r++) acc[r] = 0.f;
            #pragma unroll
            for (int i = 0; i < 4; i++) {
                int kq = lane + i * 32;
                float4 xv = xr[kq];
                #pragma unroll
                for (int r = 0; r < 16; r++) {
                    float4 av = As4[r * 128 + kq];
                    acc[r] += xv.x * av.x + xv.y * av.y + xv.z * av.z + xv.w * av.w;
                }
            }
            #pragma unroll
            for (int r = 0; r < 16; r++) {
                float v = acc[r];
                v += __shfl_xor_sync(0xFFFFFFFFu, v, 16);
                v += __shfl_xor_sync(0xFFFFFFFFu, v, 8);
                v += __shfl_xor_sync(0xFFFFFFFFu, v, 4);
                v += __shfl_xor_sync(0xFFFFFFFFu, v, 2);
                v += __shfl_xor_sync(0xFFFFFFFFu, v, 1);
                if (lane == 0) ts[(w * 8 + rr) * 16 + r] += v;
            }
        }
    }
    __syncthreads();
    #pragma unroll
    for (int j = 0; j < 4; j++)
        g_t[(size_t)blockIdx.x * 1024 + tid * 4 + j] = ts[tid * 4 + j];
}

// ---------------- kernel 2b: pack t -> bf16 [hi | lo | hi | 0] --------------
__global__ __launch_bounds__(256) void t_pack_kernel() {
    int row = blockIdx.x * 256 + threadIdx.x;         // < 8192
    const float* t = g_t + (size_t)row * 16;
    __align__(16) __nv_bfloat16 o[64];
    #pragma unroll
    for (int r = 0; r < 16; r++) {
        float f = t[r];
        __nv_bfloat16 h = __float2bfloat16(f);
        __nv_bfloat16 lo = __float2bfloat16(f - __bfloat162float(h));
        o[r] = h; o[16 + r] = lo; o[32 + r] = h; o[48 + r] = __float2bfloat16(0.f);
    }
    uint4* dst = (uint4*)(g_tA + (size_t)row * 64);
    const uint4* src = (const uint4*)o;
    #pragma unroll
    for (int j = 0; j < 8; j++) dst[j] = src[j];
}

// ---------------- kernel 2c: pack B' = 2*lora_B/scale -> [hi | hi | lo | 0] --
__global__ __launch_bounds__(256) void b_pack_kernel(const float* __restrict__ loraB,
                                                     const float* __restrict__ scale) {
    int n = blockIdx.x * 256 + threadIdx.x;           // < 4096
    float inv = 2.0f / scale[n];
    __align__(16) __nv_bfloat16 o[64];
    #pragma unroll
    for (int r = 0; r < 16; r++) {
        float v = loraB[(size_t)n * 16 + r] * inv;
        __nv_bfloat16 h = __float2bfloat16(v);
        __nv_bfloat16 lo = __float2bfloat16(v - __bfloat162float(h));
        o[r] = h; o[16 + r] = h; o[32 + r] = lo; o[48 + r] = __float2bfloat16(0.f);
    }
    uint4* dst = (uint4*)(g_tB + (size_t)n * 64);
    const uint4* src = (const uint4*)o;
    #pragma unroll
    for (int j = 0; j < 8; j++) dst[j] = src[j];
}

// ---------------- kernel 3: main split-bf16 HMMA GEMM ----------------
// CTA tile 128(M) x 128(N). Normal K-chunk: 64 f32.
// Stage layout: A f32 128x64 (32 KB, 256B rows, 16B-granule XOR swizzle)
//               B bf16 128x64 (16 KB, 128B rows, same swizzle form)
// 2 stages = 96 KB -> 2 CTAs/SM. 8 warps: warp_m = wid>>1 (32 rows),
// warp_n = wid&1 (64 cols). mma m16n8k16, per warp 2x8 accum tiles.
static constexpr int STAGE_BYTES = 49152;  // 32K A + 16K B
static constexpr int SMEM_TOTAL  = 2 * STAGE_BYTES;

DINLINE void issue_normal(const float* __restrict__ x, int m0, int n0, int c,
                          uint32_t su, int tid) {
    const float* xg = x + (size_t)m0 * 4096 + c * 64;
    #pragma unroll
    for (int i = 0; i < 8; i++) {
        int idx = tid + 256 * i;                 // < 2048 x 16B
        int row = idx >> 4, g16 = idx & 15;
        uint32_t off = (uint32_t)(row * 256 + g16 * 16);
        off ^= (uint32_t)((row & 7) << 4);
        cpa16(su + off, xg + (size_t)row * 4096 + g16 * 4);
    }
    const __nv_bfloat16* sg = g_signs_bf + (size_t)n0 * 4096 + c * 64;
    #pragma unroll
    for (int i = 0; i < 4; i++) {
        int idx = tid + 256 * i;                 // < 1024 x 16B
        int row = idx >> 3, g = idx & 7;
        uint32_t off = (uint32_t)(row * 128 + g * 16);
        off ^= (uint32_t)((row & 7) << 4);
        cpa16(su + 32768 + off, sg + (size_t)row * 4096 + g * 8);
    }
    CP_COMMIT();
}

DINLINE void issue_lora(int m0, int n0, uint32_t su, int tid) {
    #pragma unroll
    for (int i = 0; i < 4; i++) {
        int idx = tid + 256 * i;                 // < 1024 x 16B
        int row = idx >> 3, g = idx & 7;
        uint32_t off = (uint32_t)(row * 128 + g * 16);
        off ^= (uint32_t)((row & 7) << 4);
        cpa16(su + off, g_tA + (size_t)(m0 + row) * 64 + g * 8);
        cpa16(su + 32768 + off, g_tB + (size_t)(n0 + row) * 64 + g * 8);
    }
    CP_COMMIT();
}

__global__ __launch_bounds__(256, 2) void lora_gemm_kernel(
    const float* __restrict__ x, const float* __restrict__ scale,
    float* __restrict__ out) {
    extern __shared__ __align__(1024) char sm[];
    const uint32_t sbase = smem_u32(sm);
    const int tid = threadIdx.x, wid = tid >> 5, l = tid & 31;
    const int warp_m = wid >> 1, warp_n = wid & 1;
    const int n0 = blockIdx.x * 128, m0 = blockIdx.y * 128;

    float acc[2][8][4];
    #pragma unroll
    for (int i = 0; i < 2; i++)
        #pragma unroll
        for (int n = 0; n < 8; n++)
            #pragma unroll
            for (int j = 0; j < 4; j++) acc[i][n][j] = 0.f;

    // lane constants
    const uint32_t brow  = (uint32_t)((l & 7) + ((l >> 3) & 1) * 8);  // 0..15
    const uint32_t bhalf = (uint32_t)(l >> 4);                         // 0/1
    const uint32_t sxB   = (uint32_t)((l & 7) << 4);
    const uint32_t sxA   = (uint32_t)(((l >> 2) & 7) << 4);

    // ---- prologue: prefetch chunks 0, 1 ----
    issue_normal(x, m0, n0, 0, sbase, tid);
    issue_normal(x, m0, n0, 1, sbase + STAGE_BYTES, tid);

    for (int c = 0; c <= 64; c++) {
        if (c < 64) { CP_WAIT(1); } else { CP_WAIT(0); }
        __syncthreads();

        const uint32_t As = sbase + (uint32_t)(c & 1) * STAGE_BYTES;
        const uint32_t Bs = As + 32768;

        if (c < 64) {
            // ---- normal chunk: A f32 -> hi/lo split in regs, 8 mma-k-steps ----
            #pragma unroll
            for (int k16 = 0; k16 < 4; k16++) {
                uint32_t bb[8][2];
                #pragma unroll
                for (int g = 0; g < 4; g++) {
                    uint32_t addr = Bs +
                        (((uint32_t)((warp_n * 64 + g * 16 + brow) * 128)
                          + (uint32_t)(k16 * 32) + bhalf * 16) ^ sxB);
                    LDSM4(bb[2 * g][0], bb[2 * g + 1][0],
                          bb[2 * g][1], bb[2 * g + 1][1], addr);
                }
                #pragma unroll
                for (int i = 0; i < 2; i++) {
                    int row = warp_m * 32 + i * 16 + (l >> 2);
                    uint32_t base = (uint32_t)(row * 256 + k16 * 64 + (l & 3) * 8);
                    float2 v00 = lds64(As + (base ^ sxA));
                    float2 v10 = lds64(As + ((base + 2048) ^ sxA));
                    float2 v01 = lds64(As + ((base + 32) ^ sxA));
                    float2 v11 = lds64(As + ((base + 2080) ^ sxA));
                    uint32_t ah[4], al[4];
                    split2(v00, ah[0], al[0]);
                    split2(v10, ah[1], al[1]);
                    split2(v01, ah[2], al[2]);
                    split2(v11, ah[3], al[3]);
                    #pragma unroll
                    for (int n = 0; n < 8; n++) MMA16816(acc[i][n], ah, bb[n]);
                    #pragma unroll
                    for (int n = 0; n < 8; n++) MMA16816(acc[i][n], al, bb[n]);
                }
            }
        } else {
            // ---- lora chunk: both operands bf16, 3 mma-k-steps ----
            #pragma unroll
            for (int k16 = 0; k16 < 3; k16++) {
                uint32_t bb[8][2];
                #pragma unroll
                for (int g = 0; g < 4; g++) {
                    uint32_t addr = Bs +
                        (((uint32_t)((warp_n * 64 + g * 16 + brow) * 128)
                          + (uint32_t)(k16 * 32) + bhalf * 16) ^ sxB);
                    LDSM4(bb[2 * g][0], bb[2 * g + 1][0],
                          bb[2 * g][1], bb[2 * g + 1][1], addr);
                }
                #pragma unroll
                for (int i = 0; i < 2; i++) {
                    uint32_t addr = As +
                        (((uint32_t)((warp_m * 32 + i * 16 + brow) * 128)
                          + (uint32_t)(k16 * 32) + bhalf * 16) ^ sxB);
                    uint32_t ah[4];
                    LDSM4(ah[0], ah[1], ah[2], ah[3], addr);
                    #pragma unroll
                    for (int n = 0; n < 8; n++) MMA16816(acc[i][n], ah, bb[n]);
                }
            }
        }
        __syncthreads();

        if (c + 2 <= 64) {
            uint32_t su = sbase + (uint32_t)(c & 1) * STAGE_BYTES;
            if (c + 2 < 64) issue_normal(x, m0, n0, c + 2, su, tid);
            else            issue_lora(m0, n0, su, tid);
        }
    }

    // ---- epilogue: out = acc * scale[col] ----
    float* sS = (float*)sm;
    if (tid < 128) sS[tid] = scale[n0 + tid];
    __syncthreads();

    #pragma unroll
    for (int i = 0; i < 2; i++) {
        int r0 = m0 + warp_m * 32 + i * 16 + (l >> 2);
        #pragma unroll
        for (int n = 0; n < 8; n++) {
            int cl = warp_n * 64 + n * 8 + (l & 3) * 2;
            float s0 = sS[cl], s1 = sS[cl + 1];
            float2 o0 = make_float2(acc[i][n][0] * s0, acc[i][n][1] * s1);
            float2 o1 = make_float2(acc[i][n][2] * s0, acc[i][n][3] * s1);
            *(float2*)(out + (size_t)r0 * 4096 + n0 + cl) = o0;
            *(float2*)(out + (size_t)(r0 + 8) * 4096 + n0 + cl) = o1;
        }
    }
}

// ---------------- launcher ----------------
extern "C" void kernel_launch(void* const* d_in, const int* in_sizes, int n_in,
                              void* d_out, int out_size) {
    const float* x      = (const float*)d_in[0];
    const float* signs  = (const float*)d_in[1];
    const float* scale  = (const float*)d_in[2];
    const float* lora_A = (const float*)d_in[3];
    const float* lora_B = (const float*)d_in[4];
    float* out = (float*)d_out;

    convert_signs_kernel<<<8192, 256>>>(signs);
    lora_t_kernel<<<128, 256>>>(x, lora_A);
    t_pack_kernel<<<32, 256>>>();
    b_pack_kernel<<<16, 256>>>(lora_B, scale);

    cudaFuncSetAttribute(lora_gemm_kernel,
                         cudaFuncAttributeMaxDynamicSharedMemorySize, SMEM_TOTAL);
    lora_gemm_kernel<<<dim3(32, 64), 256, SMEM_TOTAL>>>(x, scale, out);
}